// round 2
// baseline (speedup 1.0000x reference)
#include <cuda_runtime.h>

#define BATCH 32
#define HID   256
#define VOCAB 10000
#define STEPS 256

// ---------------- recurrence config ----------------
#define NCTA     64          // CTAs in recurrence kernel (all co-resident)
#define DPC      4           // hidden dims owned per CTA (64*4 = 256)
#define RTHREADS 256
#define HP       260         // padded row stride for [batch][hid] smem (bank spread)

// ---------------- scratch (device globals: allocation-free) ----------------
__device__ float    g_Hs[STEPS * BATCH * HID];   // all hidden states (GEMM A matrix)
__device__ float    g_hcur[BATCH * HID];         // current h
__device__ float    g_rh[BATCH * HID];           // r * h
__device__ unsigned g_bar[2];                    // [0]=arrive (cumulative), [1]=release epoch

__global__ void bar_reset_kernel() { g_bar[0] = 0u; g_bar[1] = 0u; }

// Cumulative-epoch grid barrier. Writers fence before arrival; release is a
// release-store; spinners use acquire loads. All CTAs are resident (64 <= 148).
__device__ __forceinline__ void grid_barrier(unsigned e, unsigned ncta) {
    __syncthreads();
    if (threadIdx.x == 0) {
        __threadfence();
        unsigned a = atomicAdd(&g_bar[0], 1u);
        if (a == e * ncta - 1u) {
            asm volatile("st.release.gpu.global.u32 [%0], %1;" :: "l"(&g_bar[1]), "r"(e) : "memory");
        } else {
            unsigned v;
            do {
                asm volatile("ld.acquire.gpu.global.u32 %0, [%1];" : "=r"(v) : "l"(&g_bar[1]) : "memory");
            } while (v < e);
        }
        __threadfence();
    }
    __syncthreads();
}

// ================= Phase A: persistent GRU recurrence =================
// CTA c owns hidden output dims [4c, 4c+4) for all 32 batches.
// Weight column slices (W_hz, W_hr, W_hh restricted to those dims) live in smem
// for the whole kernel. Full h / r*h vectors are exchanged through L2 (ld/st.cg)
// with two grid barriers per step.
__global__ __launch_bounds__(RTHREADS, 1)
void rnn_kernel(const int* __restrict__ X, const float* __restrict__ H0,
                const float* __restrict__ Wxz, const float* __restrict__ Whz, const float* __restrict__ bz,
                const float* __restrict__ Wxr, const float* __restrict__ Whr, const float* __restrict__ br,
                const float* __restrict__ Wxh, const float* __restrict__ Whh, const float* __restrict__ bh,
                float* __restrict__ outF)
{
    __shared__ float Ws[3 * DPC * HP];     // [ (g*DPC+d) ][k], g: 0=z,1=r,2=h
    __shared__ float hbuf[BATCH * HP];     // staged h (phase1) then r*h (phase2)
    __shared__ float z_s[BATCH * DPC];
    __shared__ int   x_s[BATCH];

    const int tid  = threadIdx.x;
    const int dim0 = blockIdx.x * DPC;

    // Load the 3 weight column-slices once (transposed: k contiguous).
    for (int i = tid; i < 3 * DPC * HID; i += RTHREADS) {
        int g = i / (DPC * HID);
        int r = i % (DPC * HID);
        int d = r / HID;
        int k = r % HID;
        const float* W = (g == 0) ? Whz : ((g == 1) ? Whr : Whh);
        Ws[(g * DPC + d) * HP + k] = W[k * HID + dim0 + d];
    }

    // phase1 mapping: tid -> (b, gate, d)
    const int b1 = tid >> 3;
    const int g1 = (tid >> 2) & 1;
    const int d1 = tid & 3;
    // phase2 mapping: tid(<128) -> (b, d)
    const int b2 = tid >> 2;
    const int d2 = tid & 3;

    unsigned epoch = 0;

    #pragma unroll 1
    for (int t = 0; t < STEPS; ++t) {
        // ---- stage h into smem (L2-coherent loads) ----
        const float* hsrc = (t == 0) ? H0 : g_hcur;
        #pragma unroll
        for (int i = 0; i < (BATCH * HID / 4) / RTHREADS; ++i) {   // 8 float4 per thread
            int f4   = tid + i * RTHREADS;
            int flat = f4 * 4;
            int b    = flat >> 8;          // / HID
            int k    = flat & (HID - 1);
            float4 v = __ldcg(reinterpret_cast<const float4*>(hsrc + flat));
            *reinterpret_cast<float4*>(&hbuf[b * HP + k]) = v;
        }
        if (tid < BATCH) x_s[tid] = X[tid * STEPS + t];
        __syncthreads();

        // ---- phase 1: z and r gates ----
        {
            const int dim = dim0 + d1;
            const int xb  = x_s[b1];
            const float* Wx = g1 ? Wxr : Wxz;
            const float* bb = g1 ? br  : bz;
            float xg = Wx[xb * HID + dim] + bb[dim];
            const float* hrow = &hbuf[b1 * HP];
            const float* wrow = &Ws[(g1 * DPC + d1) * HP];
            float acc = 0.f;
            #pragma unroll
            for (int k = 0; k < HID; k += 4) {
                float4 h4 = *reinterpret_cast<const float4*>(hrow + k);
                float4 w4 = *reinterpret_cast<const float4*>(wrow + k);
                acc += h4.x * w4.x + h4.y * w4.y + h4.z * w4.z + h4.w * w4.w;
            }
            float pre = acc + xg;
            float s   = 1.f / (1.f + expf(-pre));
            if (g1 == 0) {
                z_s[b1 * DPC + d1] = s;
            } else {
                float rhv = s * hbuf[b1 * HP + dim];
                __stcg(&g_rh[b1 * HID + dim], rhv);
            }
        }
        grid_barrier(++epoch, gridDim.x);

        // ---- capture per-thread values still needed from hbuf (h) ----
        float hold = 0.f, zval = 0.f, xh = 0.f;
        if (tid < BATCH * DPC) {
            int dim = dim0 + d2;
            hold = hbuf[b2 * HP + dim];
            zval = z_s[b2 * DPC + d2];
            xh   = Wxh[x_s[b2] * HID + dim] + bh[dim];
        }
        __syncthreads();

        // ---- stage r*h over hbuf ----
        #pragma unroll
        for (int i = 0; i < (BATCH * HID / 4) / RTHREADS; ++i) {
            int f4   = tid + i * RTHREADS;
            int flat = f4 * 4;
            int b    = flat >> 8;
            int k    = flat & (HID - 1);
            float4 v = __ldcg(reinterpret_cast<const float4*>(g_rh + flat));
            *reinterpret_cast<float4*>(&hbuf[b * HP + k]) = v;
        }
        __syncthreads();

        // ---- phase 2: h_tilda, h_new ----
        if (tid < BATCH * DPC) {
            int dim = dim0 + d2;
            const float* rrow = &hbuf[b2 * HP];
            const float* wrow = &Ws[(2 * DPC + d2) * HP];
            float acc = 0.f;
            #pragma unroll
            for (int k = 0; k < HID; k += 4) {
                float4 r4 = *reinterpret_cast<const float4*>(rrow + k);
                float4 w4 = *reinterpret_cast<const float4*>(wrow + k);
                acc += r4.x * w4.x + r4.y * w4.y + r4.z * w4.z + r4.w * w4.w;
            }
            float htl  = tanhf(acc + xh);
            float hnew = zval * hold + (1.f - zval) * htl;
            g_Hs[(t * BATCH + b2) * HID + dim] = hnew;
            __stcg(&g_hcur[b2 * HID + dim], hnew);
            if (t == STEPS - 1) outF[b2 * HID + dim] = hnew;
        }
        grid_barrier(++epoch, gridDim.x);
    }
}

// ================= Phase B: output GEMM =================
// C[8192 x 10000] = g_Hs[8192 x 256] @ W_hq[256 x 10000] + b_q
// fp32, packed f32x2 FMA (2 MACs / FFMA2 inst). 128x128 tile, 8x8 per thread.
#define BM  128
#define BN  128
#define BKC 16
#define AST 132
#define BST 132

__device__ __forceinline__ void fma2(unsigned long long& d, unsigned long long a, unsigned long long b) {
    asm("fma.rn.f32x2 %0, %1, %2, %0;" : "+l"(d) : "l"(a), "l"(b));
}

__global__ __launch_bounds__(256, 2)
void out_gemm(const float* __restrict__ B, const float* __restrict__ bias,
              float* __restrict__ C)
{
    __shared__ float As[BKC * AST];
    __shared__ float Bs[BKC * BST];

    const int tid = threadIdx.x;
    const int tx  = tid & 15;
    const int ty  = tid >> 4;
    const int m0  = blockIdx.y * BM;
    const int n0  = blockIdx.x * BN;
    const int nth = n0 + tx * 8;

    unsigned long long acc[8][4];
    {
        float bv[8];
        #pragma unroll
        for (int j = 0; j < 8; ++j) bv[j] = (nth + j < VOCAB) ? bias[nth + j] : 0.f;
        unsigned long long p[4];
        #pragma unroll
        for (int q = 0; q < 4; ++q) {
            unsigned lo = __float_as_uint(bv[2 * q]), hi = __float_as_uint(bv[2 * q + 1]);
            asm("mov.b64 %0, {%1, %2};" : "=l"(p[q]) : "r"(lo), "r"(hi));
        }
        #pragma unroll
        for (int i = 0; i < 8; ++i)
            #pragma unroll
            for (int q = 0; q < 4; ++q) acc[i][q] = p[q];
    }

    #pragma unroll 1
    for (int k0 = 0; k0 < HID; k0 += BKC) {
        // A tile: 128 x 16, transposed into As[k][m]
        #pragma unroll
        for (int i = 0; i < 2; ++i) {
            int f4 = tid + i * 256;
            int m  = f4 >> 2;
            int kq = f4 & 3;
            float4 v = *reinterpret_cast<const float4*>(&g_Hs[(m0 + m) * HID + k0 + kq * 4]);
            As[(kq * 4 + 0) * AST + m] = v.x;
            As[(kq * 4 + 1) * AST + m] = v.y;
            As[(kq * 4 + 2) * AST + m] = v.z;
            As[(kq * 4 + 3) * AST + m] = v.w;
        }
        // B tile: 16 x 128 direct (guard last N tile)
        #pragma unroll
        for (int i = 0; i < 2; ++i) {
            int f4  = tid + i * 256;
            int kk  = f4 >> 5;
            int nq  = f4 & 31;
            int col = n0 + nq * 4;
            float4 v = make_float4(0.f, 0.f, 0.f, 0.f);
            if (col < VOCAB) v = *reinterpret_cast<const float4*>(&B[(k0 + kk) * VOCAB + col]);
            *reinterpret_cast<float4*>(&Bs[kk * BST + nq * 4]) = v;
        }
        __syncthreads();

        #pragma unroll
        for (int kk = 0; kk < BKC; ++kk) {
            float4 a0 = *reinterpret_cast<const float4*>(&As[kk * AST + ty * 8]);
            float4 a1 = *reinterpret_cast<const float4*>(&As[kk * AST + ty * 8 + 4]);
            ulonglong2 bv0 = *reinterpret_cast<const ulonglong2*>(&Bs[kk * BST + tx * 8]);
            ulonglong2 bv1 = *reinterpret_cast<const ulonglong2*>(&Bs[kk * BST + tx * 8 + 4]);
            float av[8] = {a0.x, a0.y, a0.z, a0.w, a1.x, a1.y, a1.z, a1.w};
            unsigned long long a2[8];
            #pragma unroll
            for (int i = 0; i < 8; ++i) {
                unsigned u = __float_as_uint(av[i]);
                asm("mov.b64 %0, {%1, %1};" : "=l"(a2[i]) : "r"(u));
            }
            #pragma unroll
            for (int i = 0; i < 8; ++i) {
                fma2(acc[i][0], a2[i], bv0.x);
                fma2(acc[i][1], a2[i], bv0.y);
                fma2(acc[i][2], a2[i], bv1.x);
                fma2(acc[i][3], a2[i], bv1.y);
            }
        }
        __syncthreads();
    }

    // store 8x8 per thread (guard last N tile)
    #pragma unroll
    for (int i = 0; i < 8; ++i) {
        int row = m0 + ty * 8 + i;
        float* crow = C + row * VOCAB;
        #pragma unroll
        for (int h = 0; h < 2; ++h) {
            int col = nth + h * 4;
            if (col < VOCAB) {
                float2 x0 = *reinterpret_cast<float2*>(&acc[i][2 * h]);
                float2 x1 = *reinterpret_cast<float2*>(&acc[i][2 * h + 1]);
                float4 v  = make_float4(x0.x, x0.y, x1.x, x1.y);
                *reinterpret_cast<float4*>(&crow[col]) = v;
            }
        }
    }
}

// ================= launch =================
extern "C" void kernel_launch(void* const* d_in, const int* in_sizes, int n_in,
                              void* d_out, int out_size) {
    const int*   X   = (const int*)  d_in[0];
    const float* H0  = (const float*)d_in[1];
    const float* Wxz = (const float*)d_in[2];
    const float* Whz = (const float*)d_in[3];
    const float* bz  = (const float*)d_in[4];
    const float* Wxr = (const float*)d_in[5];
    const float* Whr = (const float*)d_in[6];
    const float* br  = (const float*)d_in[7];
    const float* Wxh = (const float*)d_in[8];
    const float* Whh = (const float*)d_in[9];
    const float* bh  = (const float*)d_in[10];
    const float* Whq = (const float*)d_in[11];
    const float* bq  = (const float*)d_in[12];

    float* out  = (float*)d_out;
    float* outF = out + (out_size - BATCH * HID);   // H_final tail

    bar_reset_kernel<<<1, 1>>>();
    rnn_kernel<<<NCTA, RTHREADS>>>(X, H0, Wxz, Whz, bz, Wxr, Whr, br, Wxh, Whh, bh, outF);
    out_gemm<<<dim3((VOCAB + BN - 1) / BN, (STEPS * BATCH) / BM), 256>>>(Whq, bq, out);
}

// round 3
// speedup vs baseline: 1.2506x; 1.2506x over previous
#include <cuda_runtime.h>
#include <cuda_bf16.h>
#include <cstdint>

#define BATCH 32
#define HID   256
#define VOCAB 10000
#define STEPS 256

// ---------------- recurrence config ----------------
#define NCTA     64
#define DPC      4
#define RTHREADS 256
#define HP       260

// ---------------- scratch (device globals: allocation-free) ----------------
__device__ __nv_bfloat16 g_Ahi[STEPS * BATCH * HID];   // hidden states, bf16 hi
__device__ __nv_bfloat16 g_Alo[STEPS * BATCH * HID];   // bf16 lo (residual)
__device__ __nv_bfloat16 g_Bhi[HID * VOCAB];           // W_hq split
__device__ __nv_bfloat16 g_Blo[HID * VOCAB];
__device__ float    g_hcur[BATCH * HID];
__device__ float    g_rh[BATCH * HID];
__device__ unsigned g_bar[2];

__global__ void bar_reset_kernel() { g_bar[0] = 0u; g_bar[1] = 0u; }

__global__ void convB_kernel(const float* __restrict__ W) {
    int i = blockIdx.x * 256 + threadIdx.x;
    if (i < HID * VOCAB) {
        float v = W[i];
        __nv_bfloat16 h = __float2bfloat16(v);
        g_Bhi[i] = h;
        g_Blo[i] = __float2bfloat16(v - __bfloat162float(h));
    }
}

// grid barrier: release-arrive + acquire-spin (no full membars)
__device__ __forceinline__ void grid_barrier(unsigned e, unsigned ncta) {
    __syncthreads();
    if (threadIdx.x == 0) {
        unsigned a;
        asm volatile("atom.release.gpu.global.add.u32 %0, [%1], %2;"
                     : "=r"(a) : "l"(&g_bar[0]), "r"(1u) : "memory");
        if (a == e * ncta - 1u) {
            asm volatile("st.release.gpu.global.u32 [%0], %1;" :: "l"(&g_bar[1]), "r"(e) : "memory");
        } else {
            unsigned v;
            do {
                asm volatile("ld.acquire.gpu.global.u32 %0, [%1];" : "=r"(v) : "l"(&g_bar[1]) : "memory");
            } while (v < e);
        }
    }
    __syncthreads();
}

// ================= Phase A: persistent GRU recurrence =================
__global__ __launch_bounds__(RTHREADS, 1)
void rnn_kernel(const int* __restrict__ X, const float* __restrict__ H0,
                const float* __restrict__ Wxz, const float* __restrict__ Whz, const float* __restrict__ bz,
                const float* __restrict__ Wxr, const float* __restrict__ Whr, const float* __restrict__ br,
                const float* __restrict__ Wxh, const float* __restrict__ Whh, const float* __restrict__ bh,
                float* __restrict__ outF)
{
    __shared__ float Ws[3 * DPC * HP];
    __shared__ float hbuf[BATCH * HP];
    __shared__ float z_s[BATCH * DPC];
    __shared__ int   x_s[BATCH];

    const int tid  = threadIdx.x;
    const int dim0 = blockIdx.x * DPC;

    for (int i = tid; i < 3 * DPC * HID; i += RTHREADS) {
        int g = i / (DPC * HID);
        int r = i % (DPC * HID);
        int d = r / HID;
        int k = r % HID;
        const float* W = (g == 0) ? Whz : ((g == 1) ? Whr : Whh);
        Ws[(g * DPC + d) * HP + k] = W[k * HID + dim0 + d];
    }

    const int b1 = tid >> 3;
    const int g1 = (tid >> 2) & 1;
    const int d1 = tid & 3;
    const int b2 = tid >> 2;
    const int d2 = tid & 3;

    unsigned epoch = 0;

    #pragma unroll 1
    for (int t = 0; t < STEPS; ++t) {
        const float* hsrc = (t == 0) ? H0 : g_hcur;
        #pragma unroll
        for (int i = 0; i < (BATCH * HID / 4) / RTHREADS; ++i) {
            int f4   = tid + i * RTHREADS;
            int flat = f4 * 4;
            int b    = flat >> 8;
            int k    = flat & (HID - 1);
            float4 v = __ldcg(reinterpret_cast<const float4*>(hsrc + flat));
            *reinterpret_cast<float4*>(&hbuf[b * HP + k]) = v;
        }
        if (tid < BATCH) x_s[tid] = X[tid * STEPS + t];
        __syncthreads();

        // ---- phase 1: z and r ----
        {
            const int dim = dim0 + d1;
            const int xb  = x_s[b1];
            const float* Wx = g1 ? Wxr : Wxz;
            const float* bb = g1 ? br  : bz;
            float xg = Wx[xb * HID + dim] + bb[dim];
            const float* hrow = &hbuf[b1 * HP];
            const float* wrow = &Ws[(g1 * DPC + d1) * HP];
            float acc = 0.f;
            #pragma unroll
            for (int k = 0; k < HID; k += 4) {
                float4 h4 = *reinterpret_cast<const float4*>(hrow + k);
                float4 w4 = *reinterpret_cast<const float4*>(wrow + k);
                acc += h4.x * w4.x + h4.y * w4.y + h4.z * w4.z + h4.w * w4.w;
            }
            float pre = acc + xg;
            float s   = 1.f / (1.f + expf(-pre));
            if (g1 == 0) {
                z_s[b1 * DPC + d1] = s;
            } else {
                float rhv = s * hbuf[b1 * HP + dim];
                __stcg(&g_rh[b1 * HID + dim], rhv);
            }
        }
        grid_barrier(++epoch, gridDim.x);

        float hold = 0.f, zval = 0.f, xh = 0.f;
        if (tid < BATCH * DPC) {
            int dim = dim0 + d2;
            hold = hbuf[b2 * HP + dim];
            zval = z_s[b2 * DPC + d2];
            xh   = Wxh[x_s[b2] * HID + dim] + bh[dim];
        }
        __syncthreads();

        #pragma unroll
        for (int i = 0; i < (BATCH * HID / 4) / RTHREADS; ++i) {
            int f4   = tid + i * RTHREADS;
            int flat = f4 * 4;
            int b    = flat >> 8;
            int k    = flat & (HID - 1);
            float4 v = __ldcg(reinterpret_cast<const float4*>(g_rh + flat));
            *reinterpret_cast<float4*>(&hbuf[b * HP + k]) = v;
        }
        __syncthreads();

        // ---- phase 2: h_tilda, h_new ----
        if (tid < BATCH * DPC) {
            int dim = dim0 + d2;
            const float* rrow = &hbuf[b2 * HP];
            const float* wrow = &Ws[(2 * DPC + d2) * HP];
            float acc = 0.f;
            #pragma unroll
            for (int k = 0; k < HID; k += 4) {
                float4 r4 = *reinterpret_cast<const float4*>(rrow + k);
                float4 w4 = *reinterpret_cast<const float4*>(wrow + k);
                acc += r4.x * w4.x + r4.y * w4.y + r4.z * w4.z + r4.w * w4.w;
            }
            float htl  = tanhf(acc + xh);
            float hnew = zval * hold + (1.f - zval) * htl;
            int row = t * BATCH + b2;
            __nv_bfloat16 hb = __float2bfloat16(hnew);
            g_Ahi[row * HID + dim] = hb;
            g_Alo[row * HID + dim] = __float2bfloat16(hnew - __bfloat162float(hb));
            __stcg(&g_hcur[b2 * HID + dim], hnew);
            if (t == STEPS - 1) outF[b2 * HID + dim] = hnew;
        }
        grid_barrier(++epoch, gridDim.x);
    }
}

// ================= Phase B: output GEMM (split-bf16 tensor cores) =================
// C[8192 x 10000] = A[8192 x 256] @ B[256 x 10000] + bias
// A = Ahi+Alo, B = Bhi+Blo; D = AhiBhi + AhiBlo + AloBhi (fp32 accum).
#define GBM 128
#define GBN 128
#define GBK 16
#define GNC (HID / GBK)     // 16 k-chunks
#define GTHREADS 256

__device__ __forceinline__ uint32_t sptr(const void* p) {
    return (uint32_t)__cvta_generic_to_shared(p);
}
#define CP16(dst, src, sz) \
    asm volatile("cp.async.cg.shared.global [%0], [%1], 16, %2;" :: "r"(dst), "l"(src), "r"(sz))
#define LDSM4(r, addr) \
    asm volatile("ldmatrix.sync.aligned.m8n8.x4.shared.b16 {%0,%1,%2,%3}, [%4];" \
        : "=r"((r)[0]), "=r"((r)[1]), "=r"((r)[2]), "=r"((r)[3]) : "r"(addr))
#define LDSMT2(r, addr) \
    asm volatile("ldmatrix.sync.aligned.m8n8.x2.trans.shared.b16 {%0,%1}, [%2];" \
        : "=r"((r)[0]), "=r"((r)[1]) : "r"(addr))
#define MMA16816(d, a, b) \
    asm volatile("mma.sync.aligned.m16n8k16.row.col.f32.bf16.bf16.f32 " \
        "{%0,%1,%2,%3}, {%4,%5,%6,%7}, {%8,%9}, {%0,%1,%2,%3};" \
        : "+f"((d)[0]), "+f"((d)[1]), "+f"((d)[2]), "+f"((d)[3]) \
        : "r"((a)[0]), "r"((a)[1]), "r"((a)[2]), "r"((a)[3]), "r"((b)[0]), "r"((b)[1]))

// A smem swizzle: byte = m*32 + ((ku ^ ((m>>2)&1))<<4) + (k&7)*2   (ku = k>>3, BK=16)
// B smem swizzle: byte = k*256 + (((n>>3) ^ (k&7))<<4) + (n&7)*2
__global__ __launch_bounds__(GTHREADS, 1)
void out_gemm(const float* __restrict__ bias, float* __restrict__ C)
{
    __shared__ __align__(16) __nv_bfloat16 sAh[2][GBM * GBK];
    __shared__ __align__(16) __nv_bfloat16 sAl[2][GBM * GBK];
    __shared__ __align__(16) __nv_bfloat16 sBh[2][GBK * GBN];
    __shared__ __align__(16) __nv_bfloat16 sBl[2][GBK * GBN];

    const int tid  = threadIdx.x;
    const int lane = tid & 31;
    const int warp = tid >> 5;
    const int wm   = (warp >> 2) * 64;   // warp m offset (0/64)
    const int wn   = (warp & 3) * 32;    // warp n offset (0/32/64/96)
    const int m0   = blockIdx.y * GBM;
    const int n0   = blockIdx.x * GBN;

    float acc[4][4][4];
    #pragma unroll
    for (int i = 0; i < 4; ++i)
        #pragma unroll
        for (int j = 0; j < 4; ++j)
            #pragma unroll
            for (int q = 0; q < 4; ++q) acc[i][j][q] = 0.f;

    // ---- stage loader ----
    auto load_stage = [&](int st, int k0) {
        // A: 512 x 16B chunks (hi+lo)
        #pragma unroll
        for (int i = 0; i < 2; ++i) {
            int idx = tid + (i << 8);
            int sel = idx >> 8;
            int r   = idx & 255;
            int m   = r >> 1;
            int ku  = r & 1;
            const __nv_bfloat16* g = (sel ? g_Alo : g_Ahi) + (size_t)(m0 + m) * HID + k0 + ku * 8;
            uint32_t d = sptr(sel ? sAl[st] : sAh[st]) + m * 32 + ((ku ^ ((m >> 2) & 1)) << 4);
            CP16(d, g, 16);
        }
        // B: 512 x 16B chunks (hi+lo), guard N edge with zero-fill
        #pragma unroll
        for (int i = 0; i < 2; ++i) {
            int idx = tid + (i << 8);
            int sel = idx >> 8;
            int r   = idx & 255;
            int k   = r >> 4;
            int nu  = r & 15;
            int col = n0 + nu * 8;
            const __nv_bfloat16* g = (sel ? g_Blo : g_Bhi) + (size_t)(k0 + k) * VOCAB + col;
            uint32_t d = sptr(sel ? sBl[st] : sBh[st]) + k * 256 + ((nu ^ (k & 7)) << 4);
            int sz = (col + 8 <= VOCAB) ? 16 : 0;
            CP16(d, g, sz);
        }
    };

    load_stage(0, 0);
    asm volatile("cp.async.commit_group;");

    const int lrow = lane & 15;
    const int lkb  = (lane >> 4) & 1;

    #pragma unroll 1
    for (int c = 0; c < GNC; ++c) {
        if (c + 1 < GNC) load_stage((c + 1) & 1, (c + 1) * GBK);
        asm volatile("cp.async.commit_group;");
        asm volatile("cp.async.wait_group 1;");
        __syncthreads();

        const int st = c & 1;
        uint32_t ah[4][4], al[4][4], bh[4][2], bl[4][2];
        #pragma unroll
        for (int mt = 0; mt < 4; ++mt) {
            int m = wm + mt * 16 + lrow;
            uint32_t off = m * 32 + ((lkb ^ ((m >> 2) & 1)) << 4);
            LDSM4(ah[mt], sptr(sAh[st]) + off);
            LDSM4(al[mt], sptr(sAl[st]) + off);
        }
        #pragma unroll
        for (int nt = 0; nt < 4; ++nt) {
            int k = lrow;
            int n = wn + nt * 8;
            uint32_t off = k * 256 + (((n >> 3) ^ (k & 7)) << 4);
            LDSMT2(bh[nt], sptr(sBh[st]) + off);
            LDSMT2(bl[nt], sptr(sBl[st]) + off);
        }
        #pragma unroll
        for (int mt = 0; mt < 4; ++mt)
            #pragma unroll
            for (int nt = 0; nt < 4; ++nt) {
                MMA16816(acc[mt][nt], ah[mt], bh[nt]);
                MMA16816(acc[mt][nt], ah[mt], bl[nt]);
                MMA16816(acc[mt][nt], al[mt], bh[nt]);
            }
        __syncthreads();
    }

    // ---- epilogue: bias + store ----
    #pragma unroll
    for (int nt = 0; nt < 4; ++nt) {
        int cbase = n0 + wn + nt * 8 + 2 * (lane & 3);
        float2 bv = make_float2(0.f, 0.f);
        if (cbase + 1 < VOCAB) bv = *reinterpret_cast<const float2*>(bias + cbase);
        #pragma unroll
        for (int mt = 0; mt < 4; ++mt) {
            int r0 = m0 + wm + mt * 16 + (lane >> 2);
            if (cbase + 1 < VOCAB) {
                float2 v0 = make_float2(acc[mt][nt][0] + bv.x, acc[mt][nt][1] + bv.y);
                float2 v1 = make_float2(acc[mt][nt][2] + bv.x, acc[mt][nt][3] + bv.y);
                *reinterpret_cast<float2*>(C + (size_t)r0 * VOCAB + cbase) = v0;
                *reinterpret_cast<float2*>(C + (size_t)(r0 + 8) * VOCAB + cbase) = v1;
            }
        }
    }
}

// ================= launch =================
extern "C" void kernel_launch(void* const* d_in, const int* in_sizes, int n_in,
                              void* d_out, int out_size) {
    const int*   X   = (const int*)  d_in[0];
    const float* H0  = (const float*)d_in[1];
    const float* Wxz = (const float*)d_in[2];
    const float* Whz = (const float*)d_in[3];
    const float* bz  = (const float*)d_in[4];
    const float* Wxr = (const float*)d_in[5];
    const float* Whr = (const float*)d_in[6];
    const float* br  = (const float*)d_in[7];
    const float* Wxh = (const float*)d_in[8];
    const float* Whh = (const float*)d_in[9];
    const float* bh  = (const float*)d_in[10];
    const float* Whq = (const float*)d_in[11];
    const float* bq  = (const float*)d_in[12];

    float* out  = (float*)d_out;
    float* outF = out + (out_size - BATCH * HID);

    bar_reset_kernel<<<1, 1>>>();
    convB_kernel<<<(HID * VOCAB + 255) / 256, 256>>>(Whq);
    rnn_kernel<<<NCTA, RTHREADS>>>(X, H0, Wxz, Whz, bz, Wxr, Whr, br, Wxh, Whh, bh, outF);
    out_gemm<<<dim3((VOCAB + GBN - 1) / GBN, (STEPS * BATCH) / GBM), GTHREADS>>>(bq, out);
}